// round 1
// baseline (speedup 1.0000x reference)
#include <cuda_runtime.h>
#include <math.h>
#include <stdint.h>

// Problem constants
#define BB 8
#define TT 256
#define DD 256      // q_size / feature dim
#define HH 128
#define WW 128
#define CS 512      // c_size
#define MM (BB*TT)  // 2048 rows
#define RR 9
#define CC 9
#define KK 81       // R*C
#define ROWS 129    // H+1
#define COLS 129    // W+1

// Scratch (device globals; no allocation allowed)
__device__ float g_h[MM * 256];   // pre-tanh hidden (W_p path)
__device__ float g_u[MM * 256];   // u = c_t @ W_a
__device__ float g_p[MM * 2];     // p_t

// ---------------------------------------------------------------------------
// Kernel 1: fused GEMM. C[m, n] for n in [0,512):
//   n <  256 : g_h[m][n]      = sum_c c_t[m,c] * W_p[n,c]
//   n >= 256 : g_u[m][n-256]  = sum_c c_t[m,c] * W_a[c,n-256]
// 64x64 tiles, K-step 32, 256 threads, 4x4 micro-tile.
// ---------------------------------------------------------------------------
__global__ __launch_bounds__(256)
void gemm_kernel(const float* __restrict__ A,   // c_t (2048,512)
                 const float* __restrict__ Wp,  // (256,512)
                 const float* __restrict__ Wa)  // (512,256)
{
    __shared__ float As[64][33];
    __shared__ float Bs[32][64];

    const int m0 = blockIdx.x * 64;
    const int n0 = blockIdx.y * 64;
    const bool is_u = (n0 >= 256);
    const int tid = threadIdx.x;
    const int tx = tid & 15;        // 0..15 -> cols
    const int ty = tid >> 4;        // 0..15 -> rows

    float acc[4][4];
#pragma unroll
    for (int i = 0; i < 4; i++)
#pragma unroll
        for (int j = 0; j < 4; j++) acc[i][j] = 0.f;

    for (int k0 = 0; k0 < CS; k0 += 32) {
        // Load A tile 64x32 (float4 along k)
#pragma unroll
        for (int s = 0; s < 2; s++) {
            int f = tid + s * 256;          // float4 index, 512 total
            int row = f >> 3;
            int kk = (f & 7) << 2;
            float4 v = *(const float4*)(A + (size_t)(m0 + row) * CS + k0 + kk);
            As[row][kk + 0] = v.x; As[row][kk + 1] = v.y;
            As[row][kk + 2] = v.z; As[row][kk + 3] = v.w;
        }
        // Load B tile 32x64
        if (!is_u) {
            // B[k][n] = Wp[(n0+n)*512 + k0+k]; coalesce along k
#pragma unroll
            for (int s = 0; s < 2; s++) {
                int f = tid + s * 256;
                int n = f >> 3;
                int kk = (f & 7) << 2;
                float4 v = *(const float4*)(Wp + (size_t)(n0 + n) * CS + k0 + kk);
                Bs[kk + 0][n] = v.x; Bs[kk + 1][n] = v.y;
                Bs[kk + 2][n] = v.z; Bs[kk + 3][n] = v.w;
            }
        } else {
            // B[k][n] = Wa[(k0+k)*256 + (n0-256)+n]; coalesce along n
#pragma unroll
            for (int s = 0; s < 2; s++) {
                int f = tid + s * 256;
                int k = f >> 4;
                int nn = (f & 15) << 2;
                float4 v = *(const float4*)(Wa + (size_t)(k0 + k) * 256 + (n0 - 256) + nn);
                *(float4*)&Bs[k][nn] = v;
            }
        }
        __syncthreads();
#pragma unroll
        for (int k = 0; k < 32; k++) {
            float a[4];
#pragma unroll
            for (int i = 0; i < 4; i++) a[i] = As[ty * 4 + i][k];
            float4 b4 = *(const float4*)&Bs[k][tx * 4];
            float b[4] = {b4.x, b4.y, b4.z, b4.w};
#pragma unroll
            for (int i = 0; i < 4; i++)
#pragma unroll
                for (int j = 0; j < 4; j++)
                    acc[i][j] = fmaf(a[i], b[j], acc[i][j]);
        }
        __syncthreads();
    }

#pragma unroll
    for (int i = 0; i < 4; i++) {
        int mrow = m0 + ty * 4 + i;
#pragma unroll
        for (int j = 0; j < 4; j++) {
            int ncol = n0 + tx * 4 + j;
            if (!is_u) g_h[(size_t)mrow * 256 + ncol] = acc[i][j];
            else       g_u[(size_t)mrow * 256 + (ncol - 256)] = acc[i][j];
        }
    }
}

// ---------------------------------------------------------------------------
// Kernel 2: p_t = 128 * sigmoid( tanh(h) @ V_p^T ).  One warp per row.
// ---------------------------------------------------------------------------
__global__ __launch_bounds__(32)
void p_kernel(const float* __restrict__ Vp)  // (2,256)
{
    const int m = blockIdx.x;
    const int lane = threadIdx.x;
    float s0 = 0.f, s1 = 0.f;
    for (int n = lane; n < 256; n += 32) {
        float hv = tanhf(g_h[(size_t)m * 256 + n]);
        s0 = fmaf(hv, Vp[n], s0);
        s1 = fmaf(hv, Vp[256 + n], s1);
    }
#pragma unroll
    for (int off = 16; off > 0; off >>= 1) {
        s0 += __shfl_xor_sync(0xffffffffu, s0, off);
        s1 += __shfl_xor_sync(0xffffffffu, s1, off);
    }
    if (lane == 0) {
        g_p[m * 2 + 0] = 128.f / (1.f + expf(-s0));
        g_p[m * 2 + 1] = 128.f / (1.f + expf(-s1));
    }
}

// ---------------------------------------------------------------------------
// Kernel 3: main local attention. One CTA per (b,t). 256 threads.
// Stages the 81x256 window in shared memory, computes scores against u,
// masked softmax * gaussian, then the weighted sum over k.
// ---------------------------------------------------------------------------
__global__ __launch_bounds__(256)
void attn_kernel(const float* __restrict__ q, float* __restrict__ out)
{
    extern __shared__ float s[];           // [256][81] window, layout d*81+k
    __shared__ float su[256];
    __shared__ float spart[3 * KK];
    __shared__ float sa[KK];
    __shared__ float sw[KK];
    __shared__ float sred[2];
    __shared__ int   sri[RR], sci[CC];
    __shared__ float srex[RR], scex[CC];

    const int t = blockIdx.x;
    const int b = blockIdx.y;
    const int m = b * TT + t;
    const int tid = threadIdx.x;

    // u vector
    su[tid] = g_u[(size_t)m * 256 + tid];
    const float p0 = g_p[m * 2 + 0];
    const float p1 = g_p[m * 2 + 1];

    // indices + gaussian terms
    if (tid < RR) {
        int cr = (int)rintf(p0);
        int v = cr + tid - 3;                  // round(p0) + off + 1, off = tid-4
        v = min(max(v, 0), ROWS);
        if (v == ROWS) v = 0;
        sri[tid] = v;
        float rr = (float)max(v - 1, 0);
        float d = (rr - p0) * 0.25f;
        srex[tid] = -2.f * d * d;
    } else if (tid < RR + CC) {
        int i = tid - RR;
        int cc = (int)rintf(p1);
        int v = cc + i - 3;
        v = min(max(v, 0), COLS);
        if (v == COLS) v = 0;
        sci[i] = v;
        float ccf = (float)max(v - 1, 0);
        float d = (ccf - p1) * 0.25f;
        scex[i] = -2.f * d * d;
    }
    __syncthreads();

    // Gather window into smem: s[d*81 + k], k = i*9 + j
    const float* __restrict__ qb = q + (size_t)b * (DD * HH * WW);
#pragma unroll 9
    for (int it = 0; it < KK; ++it) {
        int e = tid + it * 256;
        int d = e / KK;
        int k = e - d * KK;
        int i = k / CC;
        int j = k - i * CC;
        int rv = sri[i];
        int cv = sci[j];
        float v = 0.f;
        if (rv > 0 && cv > 0)
            v = __ldg(&qb[(size_t)d * (HH * WW) + (size_t)(rv - 1) * WW + (cv - 1)]);
        s[d * KK + k] = v;
    }
    __syncthreads();

    // Scores: a[k] = sum_d u[d] * s[d][k], split over 3 d-partitions
    if (tid < 3 * KK) {
        int k = tid % KK;
        int part = tid / KK;
        float acc0 = 0.f, acc1 = 0.f;
        int d = part;
        for (; d + 3 < 256; d += 6) {
            acc0 = fmaf(su[d],     s[d * KK + k],       acc0);
            acc1 = fmaf(su[d + 3], s[(d + 3) * KK + k], acc1);
        }
        for (; d < 256; d += 3)
            acc0 = fmaf(su[d], s[d * KK + k], acc0);
        spart[part * KK + k] = acc0 + acc1;
    }
    __syncthreads();

    if (tid < KK) {
        float a = spart[tid] + spart[KK + tid] + spart[2 * KK + tid];
        int i = tid / CC, j = tid - i * CC;
        bool valid = (sri[i] > 0) && (sci[j] > 0);
        sa[tid] = valid ? a : -INFINITY;
    }
    __syncthreads();

    // max
    if (tid < 32) {
        float mx = -INFINITY;
        for (int k = tid; k < KK; k += 32) mx = fmaxf(mx, sa[k]);
#pragma unroll
        for (int off = 16; off > 0; off >>= 1)
            mx = fmaxf(mx, __shfl_xor_sync(0xffffffffu, mx, off));
        if (tid == 0) sred[0] = mx;
    }
    __syncthreads();
    const float mx = sred[0];
    if (tid < KK) sa[tid] = expf(sa[tid] - mx);
    __syncthreads();
    if (tid < 32) {
        float sm = 0.f;
        for (int k = tid; k < KK; k += 32) sm += sa[k];
#pragma unroll
        for (int off = 16; off > 0; off >>= 1)
            sm += __shfl_xor_sync(0xffffffffu, sm, off);
        if (tid == 0) sred[1] = sm;
    }
    __syncthreads();
    const float inv = 1.f / sred[1];
    if (tid < KK) {
        int i = tid / CC, j = tid - i * CC;
        float g = expf(srex[i] + scex[j]);
        sw[tid] = sa[tid] * inv * g;
    }
    __syncthreads();

    // Output: out[m][d] = sum_k w[k] * s[d][k]
    float o0 = 0.f, o1 = 0.f, o2 = 0.f, o3 = 0.f;
    const float* sd = &s[tid * KK];
#pragma unroll
    for (int k = 0; k < 80; k += 4) {
        o0 = fmaf(sw[k + 0], sd[k + 0], o0);
        o1 = fmaf(sw[k + 1], sd[k + 1], o1);
        o2 = fmaf(sw[k + 2], sd[k + 2], o2);
        o3 = fmaf(sw[k + 3], sd[k + 3], o3);
    }
    o0 = fmaf(sw[80], sd[80], o0);
    out[(size_t)m * DD + tid] = (o0 + o1) + (o2 + o3);
}

// ---------------------------------------------------------------------------
extern "C" void kernel_launch(void* const* d_in, const int* in_sizes, int n_in,
                              void* d_out, int out_size)
{
    const float* q   = (const float*)d_in[0];   // (8,256,128,128)
    const float* c_t = (const float*)d_in[1];   // (8,256,512)
    const float* W_a = (const float*)d_in[2];   // (512,256)
    const float* W_p = (const float*)d_in[3];   // (256,512)
    const float* V_p = (const float*)d_in[4];   // (2,256)
    float* out = (float*)d_out;                 // (8,256,256)

    // Phase 1: projections
    gemm_kernel<<<dim3(MM / 64, 512 / 64), 256>>>(c_t, W_p, W_a);
    // Phase 2: p_t
    p_kernel<<<MM, 32>>>(V_p);
    // Phase 3: attention
    const int smem = KK * DD * (int)sizeof(float);  // 82944 bytes
    cudaFuncSetAttribute(attn_kernel, cudaFuncAttributeMaxDynamicSharedMemorySize, smem);
    attn_kernel<<<dim3(TT, BB), 256, smem>>>(q, out);
}

// round 2
// speedup vs baseline: 1.0008x; 1.0008x over previous
#include <cuda_runtime.h>
#include <math.h>
#include <stdint.h>

// Problem constants
#define BB 8
#define TT 256
#define DD 256      // q_size / feature dim
#define HH 128
#define WW 128
#define CS 512      // c_size
#define MM (BB*TT)  // 2048 rows
#define RR 9
#define CC 9
#define KK 81       // R*C
#define ROWS 129    // H+1
#define COLS 129    // W+1

// Scratch (device globals; no allocation allowed)
__device__ float g_h[MM * 256];   // pre-tanh hidden (W_p path)
__device__ float g_u[MM * 256];   // u = c_t @ W_a
__device__ float g_p[MM * 2];     // p_t

// ---------------------------------------------------------------------------
// Kernel 1: fused GEMM. C[m, n] for n in [0,512):
//   n <  256 : g_h[m][n]      = sum_c c_t[m,c] * W_p[n,c]
//   n >= 256 : g_u[m][n-256]  = sum_c c_t[m,c] * W_a[c,n-256]
// 64x64 tiles, K-step 32, 256 threads, 4x4 micro-tile.
// ---------------------------------------------------------------------------
__global__ __launch_bounds__(256)
void gemm_kernel(const float* __restrict__ A,   // c_t (2048,512)
                 const float* __restrict__ Wp,  // (256,512)
                 const float* __restrict__ Wa)  // (512,256)
{
    __shared__ float As[64][33];
    __shared__ float Bs[32][64];

    const int m0 = blockIdx.x * 64;
    const int n0 = blockIdx.y * 64;
    const bool is_u = (n0 >= 256);
    const int tid = threadIdx.x;
    const int tx = tid & 15;        // 0..15 -> cols
    const int ty = tid >> 4;        // 0..15 -> rows

    float acc[4][4];
#pragma unroll
    for (int i = 0; i < 4; i++)
#pragma unroll
        for (int j = 0; j < 4; j++) acc[i][j] = 0.f;

    for (int k0 = 0; k0 < CS; k0 += 32) {
        // Load A tile 64x32 (float4 along k)
#pragma unroll
        for (int s = 0; s < 2; s++) {
            int f = tid + s * 256;          // float4 index, 512 total
            int row = f >> 3;
            int kk = (f & 7) << 2;
            float4 v = *(const float4*)(A + (size_t)(m0 + row) * CS + k0 + kk);
            As[row][kk + 0] = v.x; As[row][kk + 1] = v.y;
            As[row][kk + 2] = v.z; As[row][kk + 3] = v.w;
        }
        // Load B tile 32x64
        if (!is_u) {
            // B[k][n] = Wp[(n0+n)*512 + k0+k]; coalesce along k
#pragma unroll
            for (int s = 0; s < 2; s++) {
                int f = tid + s * 256;
                int n = f >> 3;
                int kk = (f & 7) << 2;
                float4 v = *(const float4*)(Wp + (size_t)(n0 + n) * CS + k0 + kk);
                Bs[kk + 0][n] = v.x; Bs[kk + 1][n] = v.y;
                Bs[kk + 2][n] = v.z; Bs[kk + 3][n] = v.w;
            }
        } else {
            // B[k][n] = Wa[(k0+k)*256 + (n0-256)+n]; coalesce along n
#pragma unroll
            for (int s = 0; s < 2; s++) {
                int f = tid + s * 256;
                int k = f >> 4;
                int nn = (f & 15) << 2;
                float4 v = *(const float4*)(Wa + (size_t)(k0 + k) * 256 + (n0 - 256) + nn);
                *(float4*)&Bs[k][nn] = v;
            }
        }
        __syncthreads();
#pragma unroll
        for (int k = 0; k < 32; k++) {
            float a[4];
#pragma unroll
            for (int i = 0; i < 4; i++) a[i] = As[ty * 4 + i][k];
            float4 b4 = *(const float4*)&Bs[k][tx * 4];
            float b[4] = {b4.x, b4.y, b4.z, b4.w};
#pragma unroll
            for (int i = 0; i < 4; i++)
#pragma unroll
                for (int j = 0; j < 4; j++)
                    acc[i][j] = fmaf(a[i], b[j], acc[i][j]);
        }
        __syncthreads();
    }

#pragma unroll
    for (int i = 0; i < 4; i++) {
        int mrow = m0 + ty * 4 + i;
#pragma unroll
        for (int j = 0; j < 4; j++) {
            int ncol = n0 + tx * 4 + j;
            if (!is_u) g_h[(size_t)mrow * 256 + ncol] = acc[i][j];
            else       g_u[(size_t)mrow * 256 + (ncol - 256)] = acc[i][j];
        }
    }
}

// ---------------------------------------------------------------------------
// Kernel 2: p_t = 128 * sigmoid( tanh(h) @ V_p^T ).  One warp per row.
// ---------------------------------------------------------------------------
__global__ __launch_bounds__(32)
void p_kernel(const float* __restrict__ Vp)  // (2,256)
{
    const int m = blockIdx.x;
    const int lane = threadIdx.x;
    float s0 = 0.f, s1 = 0.f;
    for (int n = lane; n < 256; n += 32) {
        float hv = tanhf(g_h[(size_t)m * 256 + n]);
        s0 = fmaf(hv, Vp[n], s0);
        s1 = fmaf(hv, Vp[256 + n], s1);
    }
#pragma unroll
    for (int off = 16; off > 0; off >>= 1) {
        s0 += __shfl_xor_sync(0xffffffffu, s0, off);
        s1 += __shfl_xor_sync(0xffffffffu, s1, off);
    }
    if (lane == 0) {
        g_p[m * 2 + 0] = 128.f / (1.f + expf(-s0));
        g_p[m * 2 + 1] = 128.f / (1.f + expf(-s1));
    }
}

// ---------------------------------------------------------------------------
// Kernel 3: main local attention. One CTA per (b,t). 256 threads.
// Stages the 81x256 window in shared memory, computes scores against u,
// masked softmax * gaussian, then the weighted sum over k.
// ---------------------------------------------------------------------------
__global__ __launch_bounds__(256)
void attn_kernel(const float* __restrict__ q, float* __restrict__ out)
{
    extern __shared__ float s[];           // [256][81] window, layout d*81+k
    __shared__ float su[256];
    __shared__ float spart[3 * KK];
    __shared__ float sa[KK];
    __shared__ float sw[KK];
    __shared__ float sred[2];
    __shared__ int   sri[RR], sci[CC];
    __shared__ float srex[RR], scex[CC];

    const int t = blockIdx.x;
    const int b = blockIdx.y;
    const int m = b * TT + t;
    const int tid = threadIdx.x;

    // u vector
    su[tid] = g_u[(size_t)m * 256 + tid];
    const float p0 = g_p[m * 2 + 0];
    const float p1 = g_p[m * 2 + 1];

    // indices + gaussian terms
    if (tid < RR) {
        int cr = (int)rintf(p0);
        int v = cr + tid - 3;                  // round(p0) + off + 1, off = tid-4
        v = min(max(v, 0), ROWS);
        if (v == ROWS) v = 0;
        sri[tid] = v;
        float rr = (float)max(v - 1, 0);
        float d = (rr - p0) * 0.25f;
        srex[tid] = -2.f * d * d;
    } else if (tid < RR + CC) {
        int i = tid - RR;
        int cc = (int)rintf(p1);
        int v = cc + i - 3;
        v = min(max(v, 0), COLS);
        if (v == COLS) v = 0;
        sci[i] = v;
        float ccf = (float)max(v - 1, 0);
        float d = (ccf - p1) * 0.25f;
        scex[i] = -2.f * d * d;
    }
    __syncthreads();

    // Gather window into smem: s[d*81 + k], k = i*9 + j
    const float* __restrict__ qb = q + (size_t)b * (DD * HH * WW);
#pragma unroll 9
    for (int it = 0; it < KK; ++it) {
        int e = tid + it * 256;
        int d = e / KK;
        int k = e - d * KK;
        int i = k / CC;
        int j = k - i * CC;
        int rv = sri[i];
        int cv = sci[j];
        float v = 0.f;
        if (rv > 0 && cv > 0)
            v = __ldg(&qb[(size_t)d * (HH * WW) + (size_t)(rv - 1) * WW + (cv - 1)]);
        s[d * KK + k] = v;
    }
    __syncthreads();

    // Scores: a[k] = sum_d u[d] * s[d][k], split over 3 d-partitions
    if (tid < 3 * KK) {
        int k = tid % KK;
        int part = tid / KK;
        float acc0 = 0.f, acc1 = 0.f;
        int d = part;
        for (; d + 3 < 256; d += 6) {
            acc0 = fmaf(su[d],     s[d * KK + k],       acc0);
            acc1 = fmaf(su[d + 3], s[(d + 3) * KK + k], acc1);
        }
        for (; d < 256; d += 3)
            acc0 = fmaf(su[d], s[d * KK + k], acc0);
        spart[part * KK + k] = acc0 + acc1;
    }
    __syncthreads();

    if (tid < KK) {
        float a = spart[tid] + spart[KK + tid] + spart[2 * KK + tid];
        int i = tid / CC, j = tid - i * CC;
        bool valid = (sri[i] > 0) && (sci[j] > 0);
        sa[tid] = valid ? a : -INFINITY;
    }
    __syncthreads();

    // max
    if (tid < 32) {
        float mx = -INFINITY;
        for (int k = tid; k < KK; k += 32) mx = fmaxf(mx, sa[k]);
#pragma unroll
        for (int off = 16; off > 0; off >>= 1)
            mx = fmaxf(mx, __shfl_xor_sync(0xffffffffu, mx, off));
        if (tid == 0) sred[0] = mx;
    }
    __syncthreads();
    const float mx = sred[0];
    if (tid < KK) sa[tid] = expf(sa[tid] - mx);
    __syncthreads();
    if (tid < 32) {
        float sm = 0.f;
        for (int k = tid; k < KK; k += 32) sm += sa[k];
#pragma unroll
        for (int off = 16; off > 0; off >>= 1)
            sm += __shfl_xor_sync(0xffffffffu, sm, off);
        if (tid == 0) sred[1] = sm;
    }
    __syncthreads();
    const float inv = 1.f / sred[1];
    if (tid < KK) {
        int i = tid / CC, j = tid - i * CC;
        float g = expf(srex[i] + scex[j]);
        sw[tid] = sa[tid] * inv * g;
    }
    __syncthreads();

    // Output: out[m][d] = sum_k w[k] * s[d][k]
    float o0 = 0.f, o1 = 0.f, o2 = 0.f, o3 = 0.f;
    const float* sd = &s[tid * KK];
#pragma unroll
    for (int k = 0; k < 80; k += 4) {
        o0 = fmaf(sw[k + 0], sd[k + 0], o0);
        o1 = fmaf(sw[k + 1], sd[k + 1], o1);
        o2 = fmaf(sw[k + 2], sd[k + 2], o2);
        o3 = fmaf(sw[k + 3], sd[k + 3], o3);
    }
    o0 = fmaf(sw[80], sd[80], o0);
    out[(size_t)m * DD + tid] = (o0 + o1) + (o2 + o3);
}

// ---------------------------------------------------------------------------
extern "C" void kernel_launch(void* const* d_in, const int* in_sizes, int n_in,
                              void* d_out, int out_size)
{
    const float* q   = (const float*)d_in[0];   // (8,256,128,128)
    const float* c_t = (const float*)d_in[1];   // (8,256,512)
    const float* W_a = (const float*)d_in[2];   // (512,256)
    const float* W_p = (const float*)d_in[3];   // (256,512)
    const float* V_p = (const float*)d_in[4];   // (2,256)
    float* out = (float*)d_out;                 // (8,256,256)

    // Phase 1: projections
    gemm_kernel<<<dim3(MM / 64, 512 / 64), 256>>>(c_t, W_p, W_a);
    // Phase 2: p_t
    p_kernel<<<MM, 32>>>(V_p);
    // Phase 3: attention
    const int smem = KK * DD * (int)sizeof(float);  // 82944 bytes
    cudaFuncSetAttribute(attn_kernel, cudaFuncAttributeMaxDynamicSharedMemorySize, smem);
    attn_kernel<<<dim3(TT, BB), 256, smem>>>(q, out);
}

// round 3
// speedup vs baseline: 1.0009x; 1.0001x over previous
#include <cuda_runtime.h>
#include <math.h>
#include <stdint.h>

// Problem constants
#define BB 8
#define TT 256
#define DD 256      // q_size / feature dim
#define HH 128
#define WW 128
#define CS 512      // c_size
#define MM (BB*TT)  // 2048 rows
#define RR 9
#define CC 9
#define KK 81       // R*C
#define ROWS 129    // H+1
#define COLS 129    // W+1

// Scratch (device globals; no allocation allowed)
__device__ float g_h[MM * 256];   // pre-tanh hidden (W_p path)
__device__ float g_u[MM * 256];   // u = c_t @ W_a
__device__ float g_p[MM * 2];     // p_t

// ---------------------------------------------------------------------------
// Kernel 1: fused GEMM. C[m, n] for n in [0,512):
//   n <  256 : g_h[m][n]      = sum_c c_t[m,c] * W_p[n,c]
//   n >= 256 : g_u[m][n-256]  = sum_c c_t[m,c] * W_a[c,n-256]
// 64x64 tiles, K-step 32, 256 threads, 4x4 micro-tile.
// ---------------------------------------------------------------------------
__global__ __launch_bounds__(256)
void gemm_kernel(const float* __restrict__ A,   // c_t (2048,512)
                 const float* __restrict__ Wp,  // (256,512)
                 const float* __restrict__ Wa)  // (512,256)
{
    __shared__ float As[64][33];
    __shared__ float Bs[32][64];

    const int m0 = blockIdx.x * 64;
    const int n0 = blockIdx.y * 64;
    const bool is_u = (n0 >= 256);
    const int tid = threadIdx.x;
    const int tx = tid & 15;        // 0..15 -> cols
    const int ty = tid >> 4;        // 0..15 -> rows

    float acc[4][4];
#pragma unroll
    for (int i = 0; i < 4; i++)
#pragma unroll
        for (int j = 0; j < 4; j++) acc[i][j] = 0.f;

    for (int k0 = 0; k0 < CS; k0 += 32) {
        // Load A tile 64x32 (float4 along k)
#pragma unroll
        for (int s = 0; s < 2; s++) {
            int f = tid + s * 256;          // float4 index, 512 total
            int row = f >> 3;
            int kk = (f & 7) << 2;
            float4 v = *(const float4*)(A + (size_t)(m0 + row) * CS + k0 + kk);
            As[row][kk + 0] = v.x; As[row][kk + 1] = v.y;
            As[row][kk + 2] = v.z; As[row][kk + 3] = v.w;
        }
        // Load B tile 32x64
        if (!is_u) {
            // B[k][n] = Wp[(n0+n)*512 + k0+k]; coalesce along k
#pragma unroll
            for (int s = 0; s < 2; s++) {
                int f = tid + s * 256;
                int n = f >> 3;
                int kk = (f & 7) << 2;
                float4 v = *(const float4*)(Wp + (size_t)(n0 + n) * CS + k0 + kk);
                Bs[kk + 0][n] = v.x; Bs[kk + 1][n] = v.y;
                Bs[kk + 2][n] = v.z; Bs[kk + 3][n] = v.w;
            }
        } else {
            // B[k][n] = Wa[(k0+k)*256 + (n0-256)+n]; coalesce along n
#pragma unroll
            for (int s = 0; s < 2; s++) {
                int f = tid + s * 256;
                int k = f >> 4;
                int nn = (f & 15) << 2;
                float4 v = *(const float4*)(Wa + (size_t)(k0 + k) * 256 + (n0 - 256) + nn);
                *(float4*)&Bs[k][nn] = v;
            }
        }
        __syncthreads();
#pragma unroll
        for (int k = 0; k < 32; k++) {
            float a[4];
#pragma unroll
            for (int i = 0; i < 4; i++) a[i] = As[ty * 4 + i][k];
            float4 b4 = *(const float4*)&Bs[k][tx * 4];
            float b[4] = {b4.x, b4.y, b4.z, b4.w};
#pragma unroll
            for (int i = 0; i < 4; i++)
#pragma unroll
                for (int j = 0; j < 4; j++)
                    acc[i][j] = fmaf(a[i], b[j], acc[i][j]);
        }
        __syncthreads();
    }

#pragma unroll
    for (int i = 0; i < 4; i++) {
        int mrow = m0 + ty * 4 + i;
#pragma unroll
        for (int j = 0; j < 4; j++) {
            int ncol = n0 + tx * 4 + j;
            if (!is_u) g_h[(size_t)mrow * 256 + ncol] = acc[i][j];
            else       g_u[(size_t)mrow * 256 + (ncol - 256)] = acc[i][j];
        }
    }
}

// ---------------------------------------------------------------------------
// Kernel 2: p_t = 128 * sigmoid( tanh(h) @ V_p^T ).  One warp per row.
// ---------------------------------------------------------------------------
__global__ __launch_bounds__(32)
void p_kernel(const float* __restrict__ Vp)  // (2,256)
{
    const int m = blockIdx.x;
    const int lane = threadIdx.x;
    float s0 = 0.f, s1 = 0.f;
    for (int n = lane; n < 256; n += 32) {
        float hv = tanhf(g_h[(size_t)m * 256 + n]);
        s0 = fmaf(hv, Vp[n], s0);
        s1 = fmaf(hv, Vp[256 + n], s1);
    }
#pragma unroll
    for (int off = 16; off > 0; off >>= 1) {
        s0 += __shfl_xor_sync(0xffffffffu, s0, off);
        s1 += __shfl_xor_sync(0xffffffffu, s1, off);
    }
    if (lane == 0) {
        g_p[m * 2 + 0] = 128.f / (1.f + expf(-s0));
        g_p[m * 2 + 1] = 128.f / (1.f + expf(-s1));
    }
}

// ---------------------------------------------------------------------------
// Kernel 3: main local attention. One CTA per (b,t). 256 threads.
// Stages the 81x256 window in shared memory, computes scores against u,
// masked softmax * gaussian, then the weighted sum over k.
// ---------------------------------------------------------------------------
__global__ __launch_bounds__(256)
void attn_kernel(const float* __restrict__ q, float* __restrict__ out)
{
    extern __shared__ float s[];           // [256][81] window, layout d*81+k
    __shared__ float su[256];
    __shared__ float spart[3 * KK];
    __shared__ float sa[KK];
    __shared__ float sw[KK];
    __shared__ float sred[2];
    __shared__ int   sri[RR], sci[CC];
    __shared__ float srex[RR], scex[CC];

    const int t = blockIdx.x;
    const int b = blockIdx.y;
    const int m = b * TT + t;
    const int tid = threadIdx.x;

    // u vector
    su[tid] = g_u[(size_t)m * 256 + tid];
    const float p0 = g_p[m * 2 + 0];
    const float p1 = g_p[m * 2 + 1];

    // indices + gaussian terms
    if (tid < RR) {
        int cr = (int)rintf(p0);
        int v = cr + tid - 3;                  // round(p0) + off + 1, off = tid-4
        v = min(max(v, 0), ROWS);
        if (v == ROWS) v = 0;
        sri[tid] = v;
        float rr = (float)max(v - 1, 0);
        float d = (rr - p0) * 0.25f;
        srex[tid] = -2.f * d * d;
    } else if (tid < RR + CC) {
        int i = tid - RR;
        int cc = (int)rintf(p1);
        int v = cc + i - 3;
        v = min(max(v, 0), COLS);
        if (v == COLS) v = 0;
        sci[i] = v;
        float ccf = (float)max(v - 1, 0);
        float d = (ccf - p1) * 0.25f;
        scex[i] = -2.f * d * d;
    }
    __syncthreads();

    // Gather window into smem: s[d*81 + k], k = i*9 + j
    const float* __restrict__ qb = q + (size_t)b * (DD * HH * WW);
#pragma unroll 9
    for (int it = 0; it < KK; ++it) {
        int e = tid + it * 256;
        int d = e / KK;
        int k = e - d * KK;
        int i = k / CC;
        int j = k - i * CC;
        int rv = sri[i];
        int cv = sci[j];
        float v = 0.f;
        if (rv > 0 && cv > 0)
            v = __ldg(&qb[(size_t)d * (HH * WW) + (size_t)(rv - 1) * WW + (cv - 1)]);
        s[d * KK + k] = v;
    }
    __syncthreads();

    // Scores: a[k] = sum_d u[d] * s[d][k], split over 3 d-partitions
    if (tid < 3 * KK) {
        int k = tid % KK;
        int part = tid / KK;
        float acc0 = 0.f, acc1 = 0.f;
        int d = part;
        for (; d + 3 < 256; d += 6) {
            acc0 = fmaf(su[d],     s[d * KK + k],       acc0);
            acc1 = fmaf(su[d + 3], s[(d + 3) * KK + k], acc1);
        }
        for (; d < 256; d += 3)
            acc0 = fmaf(su[d], s[d * KK + k], acc0);
        spart[part * KK + k] = acc0 + acc1;
    }
    __syncthreads();

    if (tid < KK) {
        float a = spart[tid] + spart[KK + tid] + spart[2 * KK + tid];
        int i = tid / CC, j = tid - i * CC;
        bool valid = (sri[i] > 0) && (sci[j] > 0);
        sa[tid] = valid ? a : -INFINITY;
    }
    __syncthreads();

    // max
    if (tid < 32) {
        float mx = -INFINITY;
        for (int k = tid; k < KK; k += 32) mx = fmaxf(mx, sa[k]);
#pragma unroll
        for (int off = 16; off > 0; off >>= 1)
            mx = fmaxf(mx, __shfl_xor_sync(0xffffffffu, mx, off));
        if (tid == 0) sred[0] = mx;
    }
    __syncthreads();
    const float mx = sred[0];
    if (tid < KK) sa[tid] = expf(sa[tid] - mx);
    __syncthreads();
    if (tid < 32) {
        float sm = 0.f;
        for (int k = tid; k < KK; k += 32) sm += sa[k];
#pragma unroll
        for (int off = 16; off > 0; off >>= 1)
            sm += __shfl_xor_sync(0xffffffffu, sm, off);
        if (tid == 0) sred[1] = sm;
    }
    __syncthreads();
    const float inv = 1.f / sred[1];
    if (tid < KK) {
        int i = tid / CC, j = tid - i * CC;
        float g = expf(srex[i] + scex[j]);
        sw[tid] = sa[tid] * inv * g;
    }
    __syncthreads();

    // Output: out[m][d] = sum_k w[k] * s[d][k]
    float o0 = 0.f, o1 = 0.f, o2 = 0.f, o3 = 0.f;
    const float* sd = &s[tid * KK];
#pragma unroll
    for (int k = 0; k < 80; k += 4) {
        o0 = fmaf(sw[k + 0], sd[k + 0], o0);
        o1 = fmaf(sw[k + 1], sd[k + 1], o1);
        o2 = fmaf(sw[k + 2], sd[k + 2], o2);
        o3 = fmaf(sw[k + 3], sd[k + 3], o3);
    }
    o0 = fmaf(sw[80], sd[80], o0);
    out[(size_t)m * DD + tid] = (o0 + o1) + (o2 + o3);
}

// ---------------------------------------------------------------------------
extern "C" void kernel_launch(void* const* d_in, const int* in_sizes, int n_in,
                              void* d_out, int out_size)
{
    const float* q   = (const float*)d_in[0];   // (8,256,128,128)
    const float* c_t = (const float*)d_in[1];   // (8,256,512)
    const float* W_a = (const float*)d_in[2];   // (512,256)
    const float* W_p = (const float*)d_in[3];   // (256,512)
    const float* V_p = (const float*)d_in[4];   // (2,256)
    float* out = (float*)d_out;                 // (8,256,256)

    // Phase 1: projections
    gemm_kernel<<<dim3(MM / 64, 512 / 64), 256>>>(c_t, W_p, W_a);
    // Phase 2: p_t
    p_kernel<<<MM, 32>>>(V_p);
    // Phase 3: attention
    const int smem = KK * DD * (int)sizeof(float);  // 82944 bytes
    cudaFuncSetAttribute(attn_kernel, cudaFuncAttributeMaxDynamicSharedMemorySize, smem);
    attn_kernel<<<dim3(TT, BB), 256, smem>>>(q, out);
}

// round 4
// speedup vs baseline: 1.0010x; 1.0001x over previous
#include <cuda_runtime.h>
#include <math.h>
#include <stdint.h>

// Problem constants
#define BB 8
#define TT 256
#define DD 256      // q_size / feature dim
#define HH 128
#define WW 128
#define CS 512      // c_size
#define MM (BB*TT)  // 2048 rows
#define RR 9
#define CC 9
#define KK 81       // R*C
#define ROWS 129    // H+1
#define COLS 129    // W+1

// Scratch (device globals; no allocation allowed)
__device__ float g_h[MM * 256];   // pre-tanh hidden (W_p path)
__device__ float g_u[MM * 256];   // u = c_t @ W_a
__device__ float g_p[MM * 2];     // p_t

// ---------------------------------------------------------------------------
// Kernel 1: fused GEMM. C[m, n] for n in [0,512):
//   n <  256 : g_h[m][n]      = sum_c c_t[m,c] * W_p[n,c]
//   n >= 256 : g_u[m][n-256]  = sum_c c_t[m,c] * W_a[c,n-256]
// 64x64 tiles, K-step 32, 256 threads, 4x4 micro-tile.
// ---------------------------------------------------------------------------
__global__ __launch_bounds__(256)
void gemm_kernel(const float* __restrict__ A,   // c_t (2048,512)
                 const float* __restrict__ Wp,  // (256,512)
                 const float* __restrict__ Wa)  // (512,256)
{
    __shared__ float As[64][33];
    __shared__ float Bs[32][64];

    const int m0 = blockIdx.x * 64;
    const int n0 = blockIdx.y * 64;
    const bool is_u = (n0 >= 256);
    const int tid = threadIdx.x;
    const int tx = tid & 15;        // 0..15 -> cols
    const int ty = tid >> 4;        // 0..15 -> rows

    float acc[4][4];
#pragma unroll
    for (int i = 0; i < 4; i++)
#pragma unroll
        for (int j = 0; j < 4; j++) acc[i][j] = 0.f;

    for (int k0 = 0; k0 < CS; k0 += 32) {
        // Load A tile 64x32 (float4 along k)
#pragma unroll
        for (int s = 0; s < 2; s++) {
            int f = tid + s * 256;          // float4 index, 512 total
            int row = f >> 3;
            int kk = (f & 7) << 2;
            float4 v = *(const float4*)(A + (size_t)(m0 + row) * CS + k0 + kk);
            As[row][kk + 0] = v.x; As[row][kk + 1] = v.y;
            As[row][kk + 2] = v.z; As[row][kk + 3] = v.w;
        }
        // Load B tile 32x64
        if (!is_u) {
            // B[k][n] = Wp[(n0+n)*512 + k0+k]; coalesce along k
#pragma unroll
            for (int s = 0; s < 2; s++) {
                int f = tid + s * 256;
                int n = f >> 3;
                int kk = (f & 7) << 2;
                float4 v = *(const float4*)(Wp + (size_t)(n0 + n) * CS + k0 + kk);
                Bs[kk + 0][n] = v.x; Bs[kk + 1][n] = v.y;
                Bs[kk + 2][n] = v.z; Bs[kk + 3][n] = v.w;
            }
        } else {
            // B[k][n] = Wa[(k0+k)*256 + (n0-256)+n]; coalesce along n
#pragma unroll
            for (int s = 0; s < 2; s++) {
                int f = tid + s * 256;
                int k = f >> 4;
                int nn = (f & 15) << 2;
                float4 v = *(const float4*)(Wa + (size_t)(k0 + k) * 256 + (n0 - 256) + nn);
                *(float4*)&Bs[k][nn] = v;
            }
        }
        __syncthreads();
#pragma unroll
        for (int k = 0; k < 32; k++) {
            float a[4];
#pragma unroll
            for (int i = 0; i < 4; i++) a[i] = As[ty * 4 + i][k];
            float4 b4 = *(const float4*)&Bs[k][tx * 4];
            float b[4] = {b4.x, b4.y, b4.z, b4.w};
#pragma unroll
            for (int i = 0; i < 4; i++)
#pragma unroll
                for (int j = 0; j < 4; j++)
                    acc[i][j] = fmaf(a[i], b[j], acc[i][j]);
        }
        __syncthreads();
    }

#pragma unroll
    for (int i = 0; i < 4; i++) {
        int mrow = m0 + ty * 4 + i;
#pragma unroll
        for (int j = 0; j < 4; j++) {
            int ncol = n0 + tx * 4 + j;
            if (!is_u) g_h[(size_t)mrow * 256 + ncol] = acc[i][j];
            else       g_u[(size_t)mrow * 256 + (ncol - 256)] = acc[i][j];
        }
    }
}

// ---------------------------------------------------------------------------
// Kernel 2: p_t = 128 * sigmoid( tanh(h) @ V_p^T ).  One warp per row.
// ---------------------------------------------------------------------------
__global__ __launch_bounds__(32)
void p_kernel(const float* __restrict__ Vp)  // (2,256)
{
    const int m = blockIdx.x;
    const int lane = threadIdx.x;
    float s0 = 0.f, s1 = 0.f;
    for (int n = lane; n < 256; n += 32) {
        float hv = tanhf(g_h[(size_t)m * 256 + n]);
        s0 = fmaf(hv, Vp[n], s0);
        s1 = fmaf(hv, Vp[256 + n], s1);
    }
#pragma unroll
    for (int off = 16; off > 0; off >>= 1) {
        s0 += __shfl_xor_sync(0xffffffffu, s0, off);
        s1 += __shfl_xor_sync(0xffffffffu, s1, off);
    }
    if (lane == 0) {
        g_p[m * 2 + 0] = 128.f / (1.f + expf(-s0));
        g_p[m * 2 + 1] = 128.f / (1.f + expf(-s1));
    }
}

// ---------------------------------------------------------------------------
// Kernel 3: main local attention. One CTA per (b,t). 256 threads.
// Stages the 81x256 window in shared memory, computes scores against u,
// masked softmax * gaussian, then the weighted sum over k.
// ---------------------------------------------------------------------------
__global__ __launch_bounds__(256)
void attn_kernel(const float* __restrict__ q, float* __restrict__ out)
{
    extern __shared__ float s[];           // [256][81] window, layout d*81+k
    __shared__ float su[256];
    __shared__ float spart[3 * KK];
    __shared__ float sa[KK];
    __shared__ float sw[KK];
    __shared__ float sred[2];
    __shared__ int   sri[RR], sci[CC];
    __shared__ float srex[RR], scex[CC];

    const int t = blockIdx.x;
    const int b = blockIdx.y;
    const int m = b * TT + t;
    const int tid = threadIdx.x;

    // u vector
    su[tid] = g_u[(size_t)m * 256 + tid];
    const float p0 = g_p[m * 2 + 0];
    const float p1 = g_p[m * 2 + 1];

    // indices + gaussian terms
    if (tid < RR) {
        int cr = (int)rintf(p0);
        int v = cr + tid - 3;                  // round(p0) + off + 1, off = tid-4
        v = min(max(v, 0), ROWS);
        if (v == ROWS) v = 0;
        sri[tid] = v;
        float rr = (float)max(v - 1, 0);
        float d = (rr - p0) * 0.25f;
        srex[tid] = -2.f * d * d;
    } else if (tid < RR + CC) {
        int i = tid - RR;
        int cc = (int)rintf(p1);
        int v = cc + i - 3;
        v = min(max(v, 0), COLS);
        if (v == COLS) v = 0;
        sci[i] = v;
        float ccf = (float)max(v - 1, 0);
        float d = (ccf - p1) * 0.25f;
        scex[i] = -2.f * d * d;
    }
    __syncthreads();

    // Gather window into smem: s[d*81 + k], k = i*9 + j
    const float* __restrict__ qb = q + (size_t)b * (DD * HH * WW);
#pragma unroll 9
    for (int it = 0; it < KK; ++it) {
        int e = tid + it * 256;
        int d = e / KK;
        int k = e - d * KK;
        int i = k / CC;
        int j = k - i * CC;
        int rv = sri[i];
        int cv = sci[j];
        float v = 0.f;
        if (rv > 0 && cv > 0)
            v = __ldg(&qb[(size_t)d * (HH * WW) + (size_t)(rv - 1) * WW + (cv - 1)]);
        s[d * KK + k] = v;
    }
    __syncthreads();

    // Scores: a[k] = sum_d u[d] * s[d][k], split over 3 d-partitions
    if (tid < 3 * KK) {
        int k = tid % KK;
        int part = tid / KK;
        float acc0 = 0.f, acc1 = 0.f;
        int d = part;
        for (; d + 3 < 256; d += 6) {
            acc0 = fmaf(su[d],     s[d * KK + k],       acc0);
            acc1 = fmaf(su[d + 3], s[(d + 3) * KK + k], acc1);
        }
        for (; d < 256; d += 3)
            acc0 = fmaf(su[d], s[d * KK + k], acc0);
        spart[part * KK + k] = acc0 + acc1;
    }
    __syncthreads();

    if (tid < KK) {
        float a = spart[tid] + spart[KK + tid] + spart[2 * KK + tid];
        int i = tid / CC, j = tid - i * CC;
        bool valid = (sri[i] > 0) && (sci[j] > 0);
        sa[tid] = valid ? a : -INFINITY;
    }
    __syncthreads();

    // max
    if (tid < 32) {
        float mx = -INFINITY;
        for (int k = tid; k < KK; k += 32) mx = fmaxf(mx, sa[k]);
#pragma unroll
        for (int off = 16; off > 0; off >>= 1)
            mx = fmaxf(mx, __shfl_xor_sync(0xffffffffu, mx, off));
        if (tid == 0) sred[0] = mx;
    }
    __syncthreads();
    const float mx = sred[0];
    if (tid < KK) sa[tid] = expf(sa[tid] - mx);
    __syncthreads();
    if (tid < 32) {
        float sm = 0.f;
        for (int k = tid; k < KK; k += 32) sm += sa[k];
#pragma unroll
        for (int off = 16; off > 0; off >>= 1)
            sm += __shfl_xor_sync(0xffffffffu, sm, off);
        if (tid == 0) sred[1] = sm;
    }
    __syncthreads();
    const float inv = 1.f / sred[1];
    if (tid < KK) {
        int i = tid / CC, j = tid - i * CC;
        float g = expf(srex[i] + scex[j]);
        sw[tid] = sa[tid] * inv * g;
    }
    __syncthreads();

    // Output: out[m][d] = sum_k w[k] * s[d][k]
    float o0 = 0.f, o1 = 0.f, o2 = 0.f, o3 = 0.f;
    const float* sd = &s[tid * KK];
#pragma unroll
    for (int k = 0; k < 80; k += 4) {
        o0 = fmaf(sw[k + 0], sd[k + 0], o0);
        o1 = fmaf(sw[k + 1], sd[k + 1], o1);
        o2 = fmaf(sw[k + 2], sd[k + 2], o2);
        o3 = fmaf(sw[k + 3], sd[k + 3], o3);
    }
    o0 = fmaf(sw[80], sd[80], o0);
    out[(size_t)m * DD + tid] = (o0 + o1) + (o2 + o3);
}

// ---------------------------------------------------------------------------
extern "C" void kernel_launch(void* const* d_in, const int* in_sizes, int n_in,
                              void* d_out, int out_size)
{
    const float* q   = (const float*)d_in[0];   // (8,256,128,128)
    const float* c_t = (const float*)d_in[1];   // (8,256,512)
    const float* W_a = (const float*)d_in[2];   // (512,256)
    const float* W_p = (const float*)d_in[3];   // (256,512)
    const float* V_p = (const float*)d_in[4];   // (2,256)
    float* out = (float*)d_out;                 // (8,256,256)

    // Phase 1: projections
    gemm_kernel<<<dim3(MM / 64, 512 / 64), 256>>>(c_t, W_p, W_a);
    // Phase 2: p_t
    p_kernel<<<MM, 32>>>(V_p);
    // Phase 3: attention
    const int smem = KK * DD * (int)sizeof(float);  // 82944 bytes
    cudaFuncSetAttribute(attn_kernel, cudaFuncAttributeMaxDynamicSharedMemorySize, smem);
    attn_kernel<<<dim3(TT, BB), 256, smem>>>(q, out);
}

// round 5
// speedup vs baseline: 1.4619x; 1.4604x over previous
#include <cuda_runtime.h>
#include <math.h>
#include <stdint.h>

// Problem constants
#define BB 8
#define TT 256
#define DD 256      // q_size / feature dim
#define HH 128
#define WW 128
#define CS 512      // c_size
#define MM (BB*TT)  // 2048 rows
#define RR 9
#define CC 9
#define KK 81       // R*C
#define ROWS 129    // H+1
#define COLS 129    // W+1
#define QTOT (8LL*256LL*16384LL)   // total floats in q

// Scratch (device globals; no allocation allowed)
__device__ float g_h[MM * 256];   // pre-tanh hidden (W_p path)
__device__ float g_u[MM * 256];   // u = c_t @ W_a
__device__ float g_p[MM * 2];     // p_t

// ---------------------------------------------------------------------------
// Kernel 1: fused GEMM with packed f32x2 FMA. C[m, n] for n in [0,512):
//   n <  256 : g_h[m][n]      = sum_c c_t[m,c] * W_p[n,c]
//   n >= 256 : g_u[m][n-256]  = sum_c c_t[m,c] * W_a[c,n-256]
// 64x64 tiles, K-step 32, 256 threads, 2x8 micro-tile (FFMA2).
// ---------------------------------------------------------------------------
__global__ __launch_bounds__(256)
void gemm_kernel(const float* __restrict__ A,   // c_t (2048,512)
                 const float* __restrict__ Wp,  // (256,512)
                 const float* __restrict__ Wa)  // (512,256)
{
    __shared__ float As[64][33];
    __shared__ float Bs[32][64];

    const int m0 = blockIdx.x * 64;
    const int n0 = blockIdx.y * 64;
    const bool is_u = (n0 >= 256);
    const int tid = threadIdx.x;
    const int tx = tid & 7;         // 0..7  -> n groups of 8
    const int ty = tid >> 3;        // 0..31 -> m pairs of 2

    unsigned long long acc[2][4];
#pragma unroll
    for (int i = 0; i < 2; i++)
#pragma unroll
        for (int j = 0; j < 4; j++) acc[i][j] = 0ull;

    for (int k0 = 0; k0 < CS; k0 += 32) {
        // Load A tile 64x32 (float4 along k)
#pragma unroll
        for (int s = 0; s < 2; s++) {
            int f = tid + s * 256;          // float4 index, 512 total
            int row = f >> 3;
            int kk = (f & 7) << 2;
            float4 v = *(const float4*)(A + (size_t)(m0 + row) * CS + k0 + kk);
            As[row][kk + 0] = v.x; As[row][kk + 1] = v.y;
            As[row][kk + 2] = v.z; As[row][kk + 3] = v.w;
        }
        // Load B tile 32x64
        if (!is_u) {
#pragma unroll
            for (int s = 0; s < 2; s++) {
                int f = tid + s * 256;
                int n = f >> 3;
                int kk = (f & 7) << 2;
                float4 v = *(const float4*)(Wp + (size_t)(n0 + n) * CS + k0 + kk);
                Bs[kk + 0][n] = v.x; Bs[kk + 1][n] = v.y;
                Bs[kk + 2][n] = v.z; Bs[kk + 3][n] = v.w;
            }
        } else {
#pragma unroll
            for (int s = 0; s < 2; s++) {
                int f = tid + s * 256;
                int k = f >> 4;
                int nn = (f & 15) << 2;
                float4 v = *(const float4*)(Wa + (size_t)(k0 + k) * 256 + (n0 - 256) + nn);
                *(float4*)&Bs[k][nn] = v;
            }
        }
        __syncthreads();
#pragma unroll
        for (int k = 0; k < 32; k++) {
            float a0 = As[ty * 2 + 0][k];
            float a1 = As[ty * 2 + 1][k];
            unsigned long long aa0, aa1;
            asm("mov.b64 %0, {%1, %2};" : "=l"(aa0) : "f"(a0), "f"(a0));
            asm("mov.b64 %0, {%1, %2};" : "=l"(aa1) : "f"(a1), "f"(a1));
            const unsigned long long* bp =
                (const unsigned long long*)&Bs[k][tx * 8];
#pragma unroll
            for (int j = 0; j < 4; j++) {
                unsigned long long bb = bp[j];
                asm("fma.rn.f32x2 %0, %1, %2, %0;" : "+l"(acc[0][j]) : "l"(aa0), "l"(bb));
                asm("fma.rn.f32x2 %0, %1, %2, %0;" : "+l"(acc[1][j]) : "l"(aa1), "l"(bb));
            }
        }
        __syncthreads();
    }

    // Epilogue: 2 rows x 8 cols per thread -> 2x2 float4 stores
#pragma unroll
    for (int e = 0; e < 2; e++) {
        int mrow = m0 + ty * 2 + e;
        float* dst;
        if (!is_u) dst = &g_h[(size_t)mrow * 256 + n0 + tx * 8];
        else       dst = &g_u[(size_t)mrow * 256 + (n0 - 256) + tx * 8];
        float2 r0 = *(float2*)&acc[e][0];
        float2 r1 = *(float2*)&acc[e][1];
        float2 r2 = *(float2*)&acc[e][2];
        float2 r3 = *(float2*)&acc[e][3];
        ((float4*)dst)[0] = make_float4(r0.x, r0.y, r1.x, r1.y);
        ((float4*)dst)[1] = make_float4(r2.x, r2.y, r3.x, r3.y);
    }
}

// ---------------------------------------------------------------------------
// Kernel 2: p_t = 128 * sigmoid( tanh(h) @ V_p^T ).  One warp per row,
// 8 rows per 256-thread block.
// ---------------------------------------------------------------------------
__global__ __launch_bounds__(256)
void p_kernel(const float* __restrict__ Vp)  // (2,256)
{
    const int m = blockIdx.x * 8 + (threadIdx.x >> 5);
    const int lane = threadIdx.x & 31;
    float s0 = 0.f, s1 = 0.f;
#pragma unroll
    for (int n = lane; n < 256; n += 32) {
        float hv = tanhf(g_h[(size_t)m * 256 + n]);
        s0 = fmaf(hv, Vp[n], s0);
        s1 = fmaf(hv, Vp[256 + n], s1);
    }
#pragma unroll
    for (int off = 16; off > 0; off >>= 1) {
        s0 += __shfl_xor_sync(0xffffffffu, s0, off);
        s1 += __shfl_xor_sync(0xffffffffu, s1, off);
    }
    if (lane == 0) {
        g_p[m * 2 + 0] = 128.f / (1.f + expf(-s0));
        g_p[m * 2 + 1] = 128.f / (1.f + expf(-s1));
    }
}

// ---------------------------------------------------------------------------
// Vectorized gather: each thread owns feature d = tid and loads its 9 window
// rows as 3 aligned float4s covering cols a0..a0+11; the 9 needed values sit
// at uniform offset OFF = (cb-4)&3. Invalid slots (clipped/wrapped -> NaN in
// reference) get softmax weight 0, so any finite value is acceptable there.
// ---------------------------------------------------------------------------
template<int OFF>
__device__ __forceinline__ void gather_rows(const float* __restrict__ q,
                                            long long gbase,   // b*4194304 + d*16384 + a0
                                            const int* __restrict__ sri,
                                            float* __restrict__ srow)  // &s[d*81]
{
#pragma unroll 3
    for (int i = 0; i < 9; i++) {
        int rv = sri[i];
        float f[12];
        if (rv > 0) {
            long long g = gbase + (long long)(rv - 1) * 128;
            if (g >= 0 && g + 12 <= QTOT) {
                float4 v0 = __ldg((const float4*)(q + g));
                float4 v1 = __ldg((const float4*)(q + g + 4));
                float4 v2 = __ldg((const float4*)(q + g + 8));
                f[0] = v0.x; f[1] = v0.y; f[2]  = v0.z; f[3]  = v0.w;
                f[4] = v1.x; f[5] = v1.y; f[6]  = v1.z; f[7]  = v1.w;
                f[8] = v2.x; f[9] = v2.y; f[10] = v2.z; f[11] = v2.w;
            } else {
                // Rare buffer-edge fallback (b==0,d==0,row==0 low / very last row high)
#pragma unroll
                for (int x = 0; x < 12; x++) {
                    long long gg = g + x;
                    f[x] = (gg >= 0 && gg < QTOT) ? __ldg(q + gg) : 0.f;
                }
            }
        } else {
#pragma unroll
            for (int x = 0; x < 12; x++) f[x] = 0.f;
        }
#pragma unroll
        for (int j = 0; j < 9; j++) srow[i * 9 + j] = f[OFF + j];
    }
}

// ---------------------------------------------------------------------------
// Kernel 3: main local attention. One CTA per (b,t). 256 threads.
// ---------------------------------------------------------------------------
__global__ __launch_bounds__(256)
void attn_kernel(const float* __restrict__ q, float* __restrict__ out)
{
    extern __shared__ float s[];           // [256][81] window, layout d*81+k
    __shared__ float su[256];
    __shared__ float spart[3 * KK];
    __shared__ float sa[KK];
    __shared__ float sw[KK];
    __shared__ float sred[2];
    __shared__ int   sri[RR], sci[CC];
    __shared__ float srex[RR], scex[CC];
    __shared__ int   scb;                  // rint(p1)

    const int t = blockIdx.x;
    const int b = blockIdx.y;
    const int m = b * TT + t;
    const int tid = threadIdx.x;

    // u vector
    su[tid] = g_u[(size_t)m * 256 + tid];
    const float p0 = g_p[m * 2 + 0];
    const float p1 = g_p[m * 2 + 1];

    // indices + gaussian terms
    if (tid < RR) {
        int cr = (int)rintf(p0);
        int v = cr + tid - 3;                  // round(p0) + off + 1, off = tid-4
        v = min(max(v, 0), ROWS);
        if (v == ROWS) v = 0;
        sri[tid] = v;
        float rr = (float)max(v - 1, 0);
        float d = (rr - p0) * 0.25f;
        srex[tid] = -2.f * d * d;
    } else if (tid < RR + CC) {
        int i = tid - RR;
        int cc = (int)rintf(p1);
        if (i == 0) scb = cc;
        int v = cc + i - 3;
        v = min(max(v, 0), COLS);
        if (v == COLS) v = 0;
        sci[i] = v;
        float ccf = (float)max(v - 1, 0);
        float d = (ccf - p1) * 0.25f;
        scex[i] = -2.f * d * d;
    }
    __syncthreads();

    // Gather window into smem: s[d*81 + k], k = i*9 + j, d = tid
    {
        const int cb = scb;
        const int a0 = (cb - 4) & ~3;          // aligned col start (may be -4)
        const int off = (cb - 4) & 3;          // uniform 0..3
        const long long gbase = (long long)b * 4194304LL
                              + (long long)tid * 16384LL + a0;
        float* srow = &s[tid * KK];
        switch (off) {
            case 0: gather_rows<0>(q, gbase, sri, srow); break;
            case 1: gather_rows<1>(q, gbase, sri, srow); break;
            case 2: gather_rows<2>(q, gbase, sri, srow); break;
            default: gather_rows<3>(q, gbase, sri, srow); break;
        }
    }
    __syncthreads();

    // Scores: a[k] = sum_d u[d] * s[d][k], split over 3 d-partitions
    if (tid < 3 * KK) {
        int k = tid % KK;
        int part = tid / KK;
        float acc0 = 0.f, acc1 = 0.f;
        int d = part;
        for (; d + 3 < 256; d += 6) {
            acc0 = fmaf(su[d],     s[d * KK + k],       acc0);
            acc1 = fmaf(su[d + 3], s[(d + 3) * KK + k], acc1);
        }
        for (; d < 256; d += 3)
            acc0 = fmaf(su[d], s[d * KK + k], acc0);
        spart[part * KK + k] = acc0 + acc1;
    }
    __syncthreads();

    if (tid < KK) {
        float a = spart[tid] + spart[KK + tid] + spart[2 * KK + tid];
        int i = tid / CC, j = tid - i * CC;
        bool valid = (sri[i] > 0) && (sci[j] > 0);
        sa[tid] = valid ? a : -INFINITY;
    }
    __syncthreads();

    // max
    if (tid < 32) {
        float mx = -INFINITY;
        for (int k = tid; k < KK; k += 32) mx = fmaxf(mx, sa[k]);
#pragma unroll
        for (int off = 16; off > 0; off >>= 1)
            mx = fmaxf(mx, __shfl_xor_sync(0xffffffffu, mx, off));
        if (tid == 0) sred[0] = mx;
    }
    __syncthreads();
    const float mx = sred[0];
    if (tid < KK) sa[tid] = expf(sa[tid] - mx);
    __syncthreads();
    if (tid < 32) {
        float sm = 0.f;
        for (int k = tid; k < KK; k += 32) sm += sa[k];
#pragma unroll
        for (int off = 16; off > 0; off >>= 1)
            sm += __shfl_xor_sync(0xffffffffu, sm, off);
        if (tid == 0) sred[1] = sm;
    }
    __syncthreads();
    const float inv = 1.f / sred[1];
    if (tid < KK) {
        int i = tid / CC, j = tid - i * CC;
        float g = expf(srex[i] + scex[j]);
        sw[tid] = sa[tid] * inv * g;
    }
    __syncthreads();

    // Output: out[m][d] = sum_k w[k] * s[d][k]
    float o0 = 0.f, o1 = 0.f, o2 = 0.f, o3 = 0.f;
    const float* sd = &s[tid * KK];
#pragma unroll
    for (int k = 0; k < 80; k += 4) {
        o0 = fmaf(sw[k + 0], sd[k + 0], o0);
        o1 = fmaf(sw[k + 1], sd[k + 1], o1);
        o2 = fmaf(sw[k + 2], sd[k + 2], o2);
        o3 = fmaf(sw[k + 3], sd[k + 3], o3);
    }
    o0 = fmaf(sw[80], sd[80], o0);
    out[(size_t)m * DD + tid] = (o0 + o1) + (o2 + o3);
}

// ---------------------------------------------------------------------------
extern "C" void kernel_launch(void* const* d_in, const int* in_sizes, int n_in,
                              void* d_out, int out_size)
{
    const float* q   = (const float*)d_in[0];   // (8,256,128,128)
    const float* c_t = (const float*)d_in[1];   // (8,256,512)
    const float* W_a = (const float*)d_in[2];   // (512,256)
    const float* W_p = (const float*)d_in[3];   // (256,512)
    const float* V_p = (const float*)d_in[4];   // (2,256)
    float* out = (float*)d_out;                 // (8,256,256)

    // Phase 1: projections
    gemm_kernel<<<dim3(MM / 64, 512 / 64), 256>>>(c_t, W_p, W_a);
    // Phase 2: p_t
    p_kernel<<<MM / 8, 256>>>(V_p);
    // Phase 3: attention
    const int smem = KK * DD * (int)sizeof(float);  // 82944 bytes
    cudaFuncSetAttribute(attn_kernel, cudaFuncAttributeMaxDynamicSharedMemorySize, smem);
    attn_kernel<<<dim3(TT, BB), 256, smem>>>(q, out);
}

// round 6
// speedup vs baseline: 1.8319x; 1.2531x over previous
#include <cuda_runtime.h>
#include <math.h>
#include <stdint.h>

// Problem constants
#define BB 8
#define TT 256
#define DD 256      // q_size / feature dim
#define HH 128
#define WW 128
#define CS 512      // c_size
#define MM (BB*TT)  // 2048 rows
#define RR 9
#define CC 9
#define KK 81       // R*C
#define ROWS 129    // H+1
#define COLS 129    // W+1
#define QTOT (8LL*256LL*16384LL)   // total floats in q

// Scratch (device globals; no allocation allowed)
__device__ float g_h[MM * 256];   // pre-tanh hidden (W_p path)
__device__ float g_u[MM * 256];   // u = c_t @ W_a
__device__ float g_p[MM * 2];     // p_t

// ---------------------------------------------------------------------------
// Kernel 1: fused GEMM, scalar FFMA 4x4 micro-tile, transposed A tile
// (LDS.128 per fragment), double-buffered smem, software-pipelined LDG.
//   n <  256 : g_h[m][n]      = sum_c c_t[m,c] * W_p[n,c]
//   n >= 256 : g_u[m][n-256]  = sum_c c_t[m,c] * W_a[c,n-256]
// ---------------------------------------------------------------------------
__global__ __launch_bounds__(256)
void gemm_kernel(const float* __restrict__ A,   // c_t (2048,512)
                 const float* __restrict__ Wp,  // (256,512)
                 const float* __restrict__ Wa)  // (512,256)
{
    __shared__ float As[2][32][68];   // [buf][k][m], stride 68 -> 16B aligned cols
    __shared__ float Bs[2][32][64];   // [buf][k][n]

    const int m0 = blockIdx.x * 64;
    const int n0 = blockIdx.y * 64;
    const bool is_u = (n0 >= 256);
    const int tid = threadIdx.x;
    const int tx = tid & 15;        // 0..15 -> n (4 cols each)
    const int ty = tid >> 4;        // 0..15 -> m (4 rows each)

    // Per-thread load coordinates (2 float4 each for A and B)
    const int a_row0 = tid >> 3;            // 0..31  (+32 for second)
    const int a_kk   = (tid & 7) << 2;      // 0,4,...,28
    // B (Wp): n = f>>3, kk = (f&7)<<2 ; B (Wa): k = f>>4, nn = (f&15)<<2
    const int bp_n0  = tid >> 3;
    const int bp_kk  = (tid & 7) << 2;
    const int ba_k0  = tid >> 4;            // 0..15 (+16 for second)
    const int ba_nn  = (tid & 15) << 2;

    float acc[4][4];
#pragma unroll
    for (int i = 0; i < 4; i++)
#pragma unroll
        for (int j = 0; j < 4; j++) acc[i][j] = 0.f;

    // ---- helpers to load a K-tile (k0) into buffer `buf` via registers ----
    float4 ra[2], rb[2];

    // Prologue: fetch tile 0
    {
        const int k0 = 0;
#pragma unroll
        for (int s = 0; s < 2; s++)
            ra[s] = *(const float4*)(A + (size_t)(m0 + a_row0 + s * 32) * CS + k0 + a_kk);
        if (!is_u) {
#pragma unroll
            for (int s = 0; s < 2; s++)
                rb[s] = *(const float4*)(Wp + (size_t)(n0 + bp_n0 + s * 32) * CS + k0 + bp_kk);
        } else {
#pragma unroll
            for (int s = 0; s < 2; s++)
                rb[s] = *(const float4*)(Wa + (size_t)(k0 + ba_k0 + s * 16) * 256 + (n0 - 256) + ba_nn);
        }
        // store to buf 0 (A transposed: As[k][m])
#pragma unroll
        for (int s = 0; s < 2; s++) {
            int row = a_row0 + s * 32;
            As[0][a_kk + 0][row] = ra[s].x;
            As[0][a_kk + 1][row] = ra[s].y;
            As[0][a_kk + 2][row] = ra[s].z;
            As[0][a_kk + 3][row] = ra[s].w;
        }
        if (!is_u) {
#pragma unroll
            for (int s = 0; s < 2; s++) {
                int n = bp_n0 + s * 32;
                Bs[0][bp_kk + 0][n] = rb[s].x;
                Bs[0][bp_kk + 1][n] = rb[s].y;
                Bs[0][bp_kk + 2][n] = rb[s].z;
                Bs[0][bp_kk + 3][n] = rb[s].w;
            }
        } else {
#pragma unroll
            for (int s = 0; s < 2; s++)
                *(float4*)&Bs[0][ba_k0 + s * 16][ba_nn] = rb[s];
        }
    }
    __syncthreads();

    int buf = 0;
    for (int k0 = 0; k0 < CS; k0 += 32) {
        const int kn = k0 + 32;
        const bool more = (kn < CS);
        // Issue next-tile global loads (no use yet -> no stall)
        if (more) {
#pragma unroll
            for (int s = 0; s < 2; s++)
                ra[s] = *(const float4*)(A + (size_t)(m0 + a_row0 + s * 32) * CS + kn + a_kk);
            if (!is_u) {
#pragma unroll
                for (int s = 0; s < 2; s++)
                    rb[s] = *(const float4*)(Wp + (size_t)(n0 + bp_n0 + s * 32) * CS + kn + bp_kk);
            } else {
#pragma unroll
                for (int s = 0; s < 2; s++)
                    rb[s] = *(const float4*)(Wa + (size_t)(kn + ba_k0 + s * 16) * 256 + (n0 - 256) + ba_nn);
            }
        }
        // Compute on current buffer (overlaps the LDGs above)
#pragma unroll
        for (int k = 0; k < 32; k++) {
            float4 a4 = *(const float4*)&As[buf][k][ty * 4];
            float4 b4 = *(const float4*)&Bs[buf][k][tx * 4];
            float a[4] = {a4.x, a4.y, a4.z, a4.w};
            float b[4] = {b4.x, b4.y, b4.z, b4.w};
#pragma unroll
            for (int i = 0; i < 4; i++)
#pragma unroll
                for (int j = 0; j < 4; j++)
                    acc[i][j] = fmaf(a[i], b[j], acc[i][j]);
        }
        // Store next tile into the other buffer
        if (more) {
            int nb = buf ^ 1;
#pragma unroll
            for (int s = 0; s < 2; s++) {
                int row = a_row0 + s * 32;
                As[nb][a_kk + 0][row] = ra[s].x;
                As[nb][a_kk + 1][row] = ra[s].y;
                As[nb][a_kk + 2][row] = ra[s].z;
                As[nb][a_kk + 3][row] = ra[s].w;
            }
            if (!is_u) {
#pragma unroll
                for (int s = 0; s < 2; s++) {
                    int n = bp_n0 + s * 32;
                    Bs[nb][bp_kk + 0][n] = rb[s].x;
                    Bs[nb][bp_kk + 1][n] = rb[s].y;
                    Bs[nb][bp_kk + 2][n] = rb[s].z;
                    Bs[nb][bp_kk + 3][n] = rb[s].w;
                }
            } else {
#pragma unroll
                for (int s = 0; s < 2; s++)
                    *(float4*)&Bs[nb][ba_k0 + s * 16][ba_nn] = rb[s];
            }
            __syncthreads();
        }
        buf ^= 1;
    }

    // Epilogue: 4x4 per thread, one float4 store per row
#pragma unroll
    for (int i = 0; i < 4; i++) {
        int mrow = m0 + ty * 4 + i;
        float4 v = make_float4(acc[i][0], acc[i][1], acc[i][2], acc[i][3]);
        if (!is_u) *(float4*)&g_h[(size_t)mrow * 256 + n0 + tx * 4] = v;
        else       *(float4*)&g_u[(size_t)mrow * 256 + (n0 - 256) + tx * 4] = v;
    }
}

// ---------------------------------------------------------------------------
// Kernel 2: p_t = 128 * sigmoid( tanh(h) @ V_p^T ).  One warp per row,
// 8 rows per 256-thread block.
// ---------------------------------------------------------------------------
__global__ __launch_bounds__(256)
void p_kernel(const float* __restrict__ Vp)  // (2,256)
{
    const int m = blockIdx.x * 8 + (threadIdx.x >> 5);
    const int lane = threadIdx.x & 31;
    float s0 = 0.f, s1 = 0.f;
#pragma unroll
    for (int n = lane; n < 256; n += 32) {
        float hv = tanhf(g_h[(size_t)m * 256 + n]);
        s0 = fmaf(hv, Vp[n], s0);
        s1 = fmaf(hv, Vp[256 + n], s1);
    }
#pragma unroll
    for (int off = 16; off > 0; off >>= 1) {
        s0 += __shfl_xor_sync(0xffffffffu, s0, off);
        s1 += __shfl_xor_sync(0xffffffffu, s1, off);
    }
    if (lane == 0) {
        g_p[m * 2 + 0] = 128.f / (1.f + expf(-s0));
        g_p[m * 2 + 1] = 128.f / (1.f + expf(-s1));
    }
}

// ---------------------------------------------------------------------------
// Vectorized gather: each thread owns feature d = tid and loads its 9 window
// rows as 3 aligned float4s covering cols a0..a0+11; the 9 needed values sit
// at uniform offset OFF = (cb-4)&3. Invalid slots (clipped/wrapped -> NaN in
// reference) get softmax weight 0, so any finite value is acceptable there.
// ---------------------------------------------------------------------------
template<int OFF>
__device__ __forceinline__ void gather_rows(const float* __restrict__ q,
                                            long long gbase,   // b*4194304 + d*16384 + a0
                                            const int* __restrict__ sri,
                                            float* __restrict__ srow)  // &s[d*81]
{
#pragma unroll 3
    for (int i = 0; i < 9; i++) {
        int rv = sri[i];
        float f[12];
        if (rv > 0) {
            long long g = gbase + (long long)(rv - 1) * 128;
            if (g >= 0 && g + 12 <= QTOT) {
                float4 v0 = __ldg((const float4*)(q + g));
                float4 v1 = __ldg((const float4*)(q + g + 4));
                float4 v2 = __ldg((const float4*)(q + g + 8));
                f[0] = v0.x; f[1] = v0.y; f[2]  = v0.z; f[3]  = v0.w;
                f[4] = v1.x; f[5] = v1.y; f[6]  = v1.z; f[7]  = v1.w;
                f[8] = v2.x; f[9] = v2.y; f[10] = v2.z; f[11] = v2.w;
            } else {
                // Rare buffer-edge fallback
#pragma unroll
                for (int x = 0; x < 12; x++) {
                    long long gg = g + x;
                    f[x] = (gg >= 0 && gg < QTOT) ? __ldg(q + gg) : 0.f;
                }
            }
        } else {
#pragma unroll
            for (int x = 0; x < 12; x++) f[x] = 0.f;
        }
#pragma unroll
        for (int j = 0; j < 9; j++) srow[i * 9 + j] = f[OFF + j];
    }
}

// ---------------------------------------------------------------------------
// Kernel 3: main local attention. One CTA per (b,t). 256 threads.
// ---------------------------------------------------------------------------
__global__ __launch_bounds__(256)
void attn_kernel(const float* __restrict__ q, float* __restrict__ out)
{
    extern __shared__ float s[];           // [256][81] window, layout d*81+k
    __shared__ float su[256];
    __shared__ float spart[3 * KK];
    __shared__ float sa[KK];
    __shared__ float sw[KK];
    __shared__ float sred[2];
    __shared__ int   sri[RR], sci[CC];
    __shared__ float srex[RR], scex[CC];
    __shared__ int   scb;                  // rint(p1)

    const int t = blockIdx.x;
    const int b = blockIdx.y;
    const int m = b * TT + t;
    const int tid = threadIdx.x;

    // u vector
    su[tid] = g_u[(size_t)m * 256 + tid];
    const float p0 = g_p[m * 2 + 0];
    const float p1 = g_p[m * 2 + 1];

    // indices + gaussian terms
    if (tid < RR) {
        int cr = (int)rintf(p0);
        int v = cr + tid - 3;                  // round(p0) + off + 1, off = tid-4
        v = min(max(v, 0), ROWS);
        if (v == ROWS) v = 0;
        sri[tid] = v;
        float rr = (float)max(v - 1, 0);
        float d = (rr - p0) * 0.25f;
        srex[tid] = -2.f * d * d;
    } else if (tid < RR + CC) {
        int i = tid - RR;
        int cc = (int)rintf(p1);
        if (i == 0) scb = cc;
        int v = cc + i - 3;
        v = min(max(v, 0), COLS);
        if (v == COLS) v = 0;
        sci[i] = v;
        float ccf = (float)max(v - 1, 0);
        float d = (ccf - p1) * 0.25f;
        scex[i] = -2.f * d * d;
    }
    __syncthreads();

    // Gather window into smem: s[d*81 + k], k = i*9 + j, d = tid
    {
        const int cb = scb;
        const int a0 = (cb - 4) & ~3;          // aligned col start (may be -4)
        const int off = (cb - 4) & 3;          // uniform 0..3
        const long long gbase = (long long)b * 4194304LL
                              + (long long)tid * 16384LL + a0;
        float* srow = &s[tid * KK];
        switch (off) {
            case 0: gather_rows<0>(q, gbase, sri, srow); break;
            case 1: gather_rows<1>(q, gbase, sri, srow); break;
            case 2: gather_rows<2>(q, gbase, sri, srow); break;
            default: gather_rows<3>(q, gbase, sri, srow); break;
        }
    }
    __syncthreads();

    // Scores: a[k] = sum_d u[d] * s[d][k], split over 3 d-partitions
    if (tid < 3 * KK) {
        int k = tid % KK;
        int part = tid / KK;
        float acc0 = 0.f, acc1 = 0.f;
        int d = part;
        for (; d + 3 < 256; d += 6) {
            acc0 = fmaf(su[d],     s[d * KK + k],       acc0);
            acc1 = fmaf(su[d + 3], s[(d + 3) * KK + k], acc1);
        }
        for (; d < 256; d += 3)
            acc0 = fmaf(su[d], s[d * KK + k], acc0);
        spart[part * KK + k] = acc0 + acc1;
    }
    __syncthreads();

    if (tid < KK) {
        float a = spart[tid] + spart[KK + tid] + spart[2 * KK + tid];
        int i = tid / CC, j = tid - i * CC;
        bool valid = (sri[i] > 0) && (sci[j] > 0);
        sa[tid] = valid ? a : -INFINITY;
    }
    __syncthreads();

    // max
    if (tid < 32) {
        float mx = -INFINITY;
        for (int k = tid; k < KK; k += 32) mx = fmaxf(mx, sa[k]);
#pragma unroll
        for (int off = 16; off > 0; off >>= 1)
            mx = fmaxf(mx, __shfl_xor_sync(0xffffffffu, mx, off));
        if (tid == 0) sred[0] = mx;
    }
    __syncthreads();
    const float mx = sred[0];
    if (tid < KK) sa[tid] = expf(sa[tid] - mx);
    __syncthreads();
    if (tid < 32) {
        float sm = 0.f;
        for (int k = tid; k < KK; k += 32) sm += sa[k];
#pragma unroll
        for (int off = 16; off > 0; off >>= 1)
            sm += __shfl_xor_sync(0xffffffffu, sm, off);
        if (tid == 0) sred[1] = sm;
    }
    __syncthreads();
    const float inv = 1.f / sred[1];
    if (tid < KK) {
        int i = tid / CC, j = tid - i * CC;
        float g = expf(srex[i] + scex[j]);
        sw[tid] = sa[tid] * inv * g;
    }
    __syncthreads();

    // Output: out[m][d] = sum_k w[k] * s[d][k]
    float o0 = 0.f, o1 = 0.f, o2 = 0.f, o3 = 0.f;
    const float* sd = &s[tid * KK];
#pragma unroll
    for (int k = 0; k < 80; k += 4) {
        o0 = fmaf(sw[k + 0], sd[k + 0], o0);
        o1 = fmaf(sw[k + 1], sd[k + 1], o1);
        o2 = fmaf(sw[k + 2], sd[k + 2], o2);
        o3 = fmaf(sw[k + 3], sd[k + 3], o3);
    }
    o0 = fmaf(sw[80], sd[80], o0);
    out[(size_t)m * DD + tid] = (o0 + o1) + (o2 + o3);
}

// ---------------------------------------------------------------------------
extern "C" void kernel_launch(void* const* d_in, const int* in_sizes, int n_in,
                              void* d_out, int out_size)
{
    const float* q   = (const float*)d_in[0];   // (8,256,128,128)
    const float* c_t = (const float*)d_in[1];   // (8,256,512)
    const float* W_a = (const float*)d_in[2];   // (512,256)
    const float* W_p = (const float*)d_in[3];   // (256,512)
    const float* V_p = (const float*)d_in[4];   // (2,256)
    float* out = (float*)d_out;                 // (8,256,256)

    // Phase 1: projections
    gemm_kernel<<<dim3(MM / 64, 512 / 64), 256>>>(c_t, W_p, W_a);
    // Phase 2: p_t
    p_kernel<<<MM / 8, 256>>>(V_p);
    // Phase 3: attention
    const int smem = KK * DD * (int)sizeof(float);  // 82944 bytes
    cudaFuncSetAttribute(attn_kernel, cudaFuncAttributeMaxDynamicSharedMemorySize, smem);
    attn_kernel<<<dim3(TT, BB), 256, smem>>>(q, out);
}